// round 13
// baseline (speedup 1.0000x reference)
#include <cuda_runtime.h>
#include <math.h>
#include <cstdint>

#define BSZ 1024
#define PP  128
#define SSZ 128
#define NNODE 168
#define NHH 4
#define HGG 128

// ---------------- static scratch (allocation-free rule) ----------------
__device__ float g_Xf[BSZ*PP*40];
__device__ float g_T1[BSZ*40*64];
__device__ float g_As[BSZ*40*40];
__device__ float g_T2[BSZ*PP*64];
__device__ float g_At[BSZ*PP*PP];
__device__ float g_Ms[BSZ*40*PP];
__device__ float g_Mt[BSZ*PP*40];
__device__ float g_H [BSZ*NNODE*HGG];
__device__ float g_Q [BSZ*NHH*NNODE*HGG];
__device__ float g_K [BSZ*NHH*NNODE*HGG];
__device__ float g_V [BSZ*NHH*NNODE*HGG];
__device__ float g_S [BSZ*NHH*NNODE*NNODE];
__device__ float g_O [BSZ*NHH*NNODE*HGG];

// ---------------- block reduction helpers (128 threads) ----------------
__device__ __forceinline__ float4 bsum4(float4 v, float4* red){
    int tid = threadIdx.x;
    __syncthreads();
    red[tid] = v;
    __syncthreads();
    #pragma unroll
    for (int o = 64; o > 0; o >>= 1){
        if (tid < o){
            float4 a = red[tid], b = red[tid+o];
            a.x += b.x; a.y += b.y; a.z += b.z; a.w += b.w;
            red[tid] = a;
        }
        __syncthreads();
    }
    return red[0];
}

__device__ __forceinline__ float2 bmax2(float2 v, float4* red){
    int tid = threadIdx.x;
    __syncthreads();
    red[tid] = make_float4(v.x, v.y, 0.f, 0.f);
    __syncthreads();
    #pragma unroll
    for (int o = 64; o > 0; o >>= 1){
        if (tid < o){
            red[tid].x = fmaxf(red[tid].x, red[tid+o].x);
            red[tid].y = fmaxf(red[tid].y, red[tid+o].y);
        }
        __syncthreads();
    }
    return make_float2(red[0].x, red[0].y);
}

// ---------------- K1: per-row feature extraction ----------------
__global__ void feat_kernel(const float* __restrict__ X, float* __restrict__ Xf){
    __shared__ float s[128], ctab[128], stab[128], psd[128], av[128];
    __shared__ float4 red[128];
    __shared__ float sel[2];
    int row = blockIdx.x;
    int tid = threadIdx.x;

    float x = X[(size_t)row*128 + tid];
    s[tid] = x;
    float sv, cv;
    sincospif((float)tid * (1.0f/64.0f), &sv, &cv);
    ctab[tid] = cv; stab[tid] = sv;

    float2 mm2 = bmax2(make_float2(x, -x), red);
    float mx = mm2.x, mn = -mm2.y;

    float xc  = fminf(fmaxf(x, -0.99999988f), 0.99999988f);
    float asn = asinf(xc);
    float atn = atanf(x);
    float4 r1 = bsum4(make_float4(x, x*x, asn, atn), red);
    float mean    = r1.x * (1.0f/128.0f);
    float rms     = sqrtf(r1.y * (1.0f/128.0f));
    float mean_as = r1.z * (1.0f/128.0f);
    float mean_at = r1.w * (1.0f/128.0f);

    float cen = x - mean;
    float c2  = cen*cen;
    float e   = expf(x - mx);
    float4 r2 = bsum4(make_float4(c2, c2*cen, c2*c2, e), red);
    float var  = r2.x * (1.0f/127.0f);
    float stdv = sqrtf(var);
    float se   = r2.w;

    float da = asn - mean_as, dt = atn - mean_at;
    float4 r3 = bsum4(make_float4(e*x, da*da, dt*dt, 0.f), red);
    float ent      = (mx + logf(se)) - r3.x / se;
    float std_asin = sqrtf(r3.y * (1.0f/127.0f));
    float std_atan = sqrtf(r3.z * (1.0f/127.0f));
    float kurt = (r2.z * (1.0f/128.0f)) / (var*var)  - 3.0f;
    float skew = (r2.y * (1.0f/128.0f)) / (var*stdv);

    if (tid <= 64){
        float re = 0.f, im = 0.f;
        int j = 0;
        #pragma unroll 8
        for (int t = 0; t < 128; ++t){
            float st = s[t];
            re += st * ctab[j];
            im -= st * stab[j];
            j = (j + tid) & 127;
        }
        float a2 = re*re + im*im;
        av[tid]  = sqrtf(a2);
        psd[tid] = a2 * (1.0f/128.0f);
    }
    __syncthreads();
    if (tid > 64){ psd[tid] = psd[128-tid]; av[tid] = av[128-tid]; }
    __syncthreads();

    float pj = psd[tid];
    float aj = av[tid];
    float fj = (float)((tid < 64) ? tid : tid - 128) * (1.0f/128.0f);
    float4 r4 = bsum4(make_float4(pj, pj*pj, fj*pj, 0.f), red);
    float psum      = r4.x;
    float mean_freq = r4.z / psum;
    float pbw       = sqrtf(r4.y / psum);
    float2 m2 = bmax2(make_float2(pj, aj), red);
    float max_psd = m2.x, max_amp = m2.y;

    int rank = 0, gc = 0;
    #pragma unroll 4
    for (int i = 0; i < 128; ++i){
        float pi = psd[i];
        rank += (pi < pj) || (pi == pj && i < tid);
        float ai = av[i];
        gc   += (ai > aj) || (ai == aj && i < tid);
    }
    if (rank == 64) sel[0] = fj;
    if (gc == 0)    sel[1] = fj;
    __syncthreads();

    if (tid == 0){
        float* o = Xf + (size_t)row*40;
        o[0]=mx; o[1]=mn; o[2]=stdv; o[3]=rms; o[4]=mean; o[5]=mx-mn; o[6]=var;
        o[7]=ent; o[8]=std_asin; o[9]=std_atan; o[10]=kurt; o[11]=skew;
        o[12]=mean_freq; o[13]=sel[0]; o[14]=psum; o[15]=1.0f; o[16]=pbw;
        o[17]=max_psd; o[18]=max_amp; o[19]=sel[1];
    }
}

// ---------------- K2: cumsum features + per-batch L2 normalization ----------------
__global__ void cum_norm_kernel(float* __restrict__ Xf){
    __shared__ float red[256];
    int b = blockIdx.x;
    float* F = Xf + (size_t)b*5120;
    int tid = threadIdx.x;
    if (tid < 20){
        float c = 0.f;
        for (int p = 0; p < 128; ++p){
            c += F[p*40 + tid];
            F[p*40 + 20 + tid] = c / sqrtf(fmaxf(fabsf(c), 1e-12f));
        }
    }
    __syncthreads();
    float ss = 0.f;
    for (int i = tid; i < 5120; i += 256){ float v = F[i]; ss += v*v; }
    red[tid] = ss; __syncthreads();
    #pragma unroll
    for (int o = 128; o > 0; o >>= 1){ if (tid < o) red[tid] += red[tid+o]; __syncthreads(); }
    float inv = 1.0f / sqrtf(red[0]);
    for (int i = tid; i < 5120; i += 256) F[i] *= inv;
}

// ---------------- templated strided batched GEMM, double-buffered, vectorized ----------------
// Guarded (ceil-count) staging: supports NT that does not divide BM*BK / BN*BK.
template<int BM, int BN, int BK, int TM, int TN, bool AV, bool BV>
__global__ void __launch_bounds__((BM/TM)*(BN/TN)) bgemm_t(
    const float* __restrict__ A, long long sAb, int sAr, int sAc, int aDiv,
    const float* __restrict__ B, long long sBb, int sBr, int sBc, int bMod,
    const float* __restrict__ bias, int biasStride,
    float* __restrict__ C, long long sCb, int ldc,
    int M, int N, int K, float alpha, int act)
{
    constexpr int TPN = BN / TN;
    constexpr int TPM = BM / TM;
    constexpr int NT  = TPN * TPM;
    constexpr int BK4 = BK/4;
    constexpr int BN4 = BN/4;
    constexpr int AL4C = (BM*BK4 + NT - 1)/NT;   // vector A stage count
    constexpr int ALC  = (BM*BK  + NT - 1)/NT;   // scalar A stage count
    constexpr int BL4C = (BK*BN4 + NT - 1)/NT;   // vector B stage count
    constexpr int BLC  = (BN*BK  + NT - 1)/NT;   // scalar B stage count
    __shared__ float As[2][BK][BM+4];
    __shared__ float Bs[2][BK][BN+4];

    int z = blockIdx.z;
    const float* Ab = A + (size_t)((aDiv > 1) ? (z / aDiv) : z) * (size_t)sAb;
    const float* Bb = B + (size_t)((bMod == 0) ? z : (z % bMod)) * (size_t)sBb;
    const float* biasb = bias ? (bias + (size_t)((bMod > 1) ? (z % bMod) : 0) * (size_t)biasStride) : (const float*)0;
    float* Cb = C + (size_t)z * (size_t)sCb;

    int row0 = blockIdx.y * BM, col0 = blockIdx.x * BN;
    int tid = threadIdx.x;
    int tx = tid % TPN, ty = tid / TPN;

    float acc[TM][TN];
    #pragma unroll
    for (int i = 0; i < TM; ++i)
        #pragma unroll
        for (int j = 0; j < TN; ++j) acc[i][j] = 0.f;

    float4 ra4[AV ? AL4C : 1];
    float  ra [AV ? 1 : ALC];
    float4 rb4[BV ? BL4C : 1];
    float  rb [BV ? 1 : BLC];

    auto fetch = [&](int k0){
        if constexpr (AV){
            #pragma unroll
            for (int u = 0; u < AL4C; ++u){
                int i = tid + u*NT;
                if (i < BM*BK4){
                    int kk4 = i % BK4, mm = i / BK4;
                    int gm = row0 + mm;
                    ra4[u] = (gm < M) ? *(const float4*)(Ab + (size_t)gm*sAr + (k0 + kk4*4))
                                      : make_float4(0.f,0.f,0.f,0.f);
                }
            }
        } else {
            #pragma unroll
            for (int u = 0; u < ALC; ++u){
                int i = tid + u*NT;
                if (i < BM*BK){
                    int kk = i / BM, mm = i % BM;
                    int gm = row0 + mm, gk = k0 + kk;
                    ra[u] = (gm < M) ? Ab[(size_t)gm*sAr + (size_t)gk*sAc] : 0.f;
                }
            }
        }
        if constexpr (BV){
            #pragma unroll
            for (int u = 0; u < BL4C; ++u){
                int i = tid + u*NT;
                if (i < BK*BN4){
                    int kk = i / BN4, nn4 = i % BN4;
                    int gn = col0 + nn4*4, gk = k0 + kk;
                    rb4[u] = (gn < N) ? *(const float4*)(Bb + (size_t)gk*sBr + gn)
                                      : make_float4(0.f,0.f,0.f,0.f);
                }
            }
        } else {
            #pragma unroll
            for (int u = 0; u < BLC; ++u){
                int i = tid + u*NT;
                if (i < BN*BK){
                    int kk = i / BN, nn = i % BN;
                    int gn = col0 + nn, gk = k0 + kk;
                    rb[u] = (gn < N) ? Bb[(size_t)gk*sBr + (size_t)gn*sBc] : 0.f;
                }
            }
        }
    };
    auto stage = [&](int sIdx){
        if constexpr (AV){
            #pragma unroll
            for (int u = 0; u < AL4C; ++u){
                int i = tid + u*NT;
                if (i < BM*BK4){
                    int kk4 = i % BK4, mm = i / BK4;
                    As[sIdx][kk4*4+0][mm] = ra4[u].x;
                    As[sIdx][kk4*4+1][mm] = ra4[u].y;
                    As[sIdx][kk4*4+2][mm] = ra4[u].z;
                    As[sIdx][kk4*4+3][mm] = ra4[u].w;
                }
            }
        } else {
            #pragma unroll
            for (int u = 0; u < ALC; ++u){
                int i = tid + u*NT;
                if (i < BM*BK) As[sIdx][i / BM][i % BM] = ra[u];
            }
        }
        if constexpr (BV){
            #pragma unroll
            for (int u = 0; u < BL4C; ++u){
                int i = tid + u*NT;
                if (i < BK*BN4){
                    int kk = i / BN4, nn4 = i % BN4;
                    *(float4*)&Bs[sIdx][kk][nn4*4] = rb4[u];
                }
            }
        } else {
            #pragma unroll
            for (int u = 0; u < BLC; ++u){
                int i = tid + u*NT;
                if (i < BN*BK) Bs[sIdx][i / BN][i % BN] = rb[u];
            }
        }
    };

    fetch(0);
    stage(0);
    __syncthreads();

    int nk = K / BK;
    for (int t = 0; t < nk; ++t){
        int cur = t & 1, nxt = cur ^ 1;
        if (t + 1 < nk) fetch((t + 1) * BK);
        #pragma unroll
        for (int kk = 0; kk < BK; ++kk){
            float a[TM], b[TN];
            #pragma unroll
            for (int i = 0; i < TM; i += 4)
                *(float4*)&a[i] = *(const float4*)&As[cur][kk][ty*TM + i];
            #pragma unroll
            for (int j = 0; j < TN; j += 4)
                *(float4*)&b[j] = *(const float4*)&Bs[cur][kk][tx*TN + j];
            #pragma unroll
            for (int i = 0; i < TM; ++i)
                #pragma unroll
                for (int j = 0; j < TN; ++j)
                    acc[i][j] += a[i]*b[j];
        }
        if (t + 1 < nk) stage(nxt);
        __syncthreads();
    }

    #pragma unroll
    for (int i = 0; i < TM; ++i){
        int gm = row0 + ty*TM + i;
        if (gm >= M) continue;
        #pragma unroll
        for (int j4 = 0; j4 < TN; j4 += 4){
            int gn = col0 + tx*TN + j4;
            if (gn >= N) continue;
            float4 v;
            float* vp = &v.x;
            #pragma unroll
            for (int c = 0; c < 4; ++c){
                float w = acc[i][j4+c] * alpha;
                if (biasb) w += biasb[gn+c];
                if (act == 1)      w = tanhf(w);
                else if (act == 2) w = (w >= 0.f) ? w : 0.01f*w;
                vp[c] = w;
            }
            *(float4*)(Cb + (size_t)gm*ldc + gn) = v;
        }
    }
}

// Tile variants
#define GBIG   bgemm_t<64,128,8,8,8,true,true>      // 128 thr
#define GSML   bgemm_t<64,64,8,8,8,true,true>       // 64 thr
#define GA     bgemm_t<40,64,8,8,8,false,true>      // 40 thr  (a)
#define GE     bgemm_t<40,128,8,8,8,true,false>     // 80 thr  (e)
#define GF     bgemm_t<40,128,8,8,8,true,true>      // 80 thr  (f)
#define GG     bgemm_t<128,40,8,8,8,true,true>      // 80 thr  (g)
#define GJ     bgemm_t<56,64,8,8,8,true,false>      // 56 thr  (j) scores
#define GL     bgemm_t<56,128,8,8,8,true,true>      // 112 thr (l) attn@V

// ---------------- stacked QKV GEMM ----------------
// grid (2688, 12): x = 64-row tile of stacked H (172032x128), y = qkv*4+h.
// C scatter: row gr -> b=gr/168, n=gr%168; dst[((b*4+h)*168+n)*128 + col].
__global__ void __launch_bounds__(128) qkv_gemm(
    const float* __restrict__ H,
    const float* __restrict__ qw, const float* __restrict__ kw, const float* __restrict__ vw,
    const float* __restrict__ qb, const float* __restrict__ kb, const float* __restrict__ vb,
    float* __restrict__ Qo, float* __restrict__ Ko, float* __restrict__ Vo)
{
    __shared__ float As[2][8][68];
    __shared__ float Bs[2][8][132];
    const int tid = threadIdx.x;
    const int row0 = blockIdx.x * 64;
    const int y = blockIdx.y;
    const int qkv = y >> 2, h = y & 3;
    const float* W    = ((qkv == 0) ? qw : (qkv == 1) ? kw : vw) + h*16384;  // [k][n], n contiguous
    const float* bias = ((qkv == 0) ? qb : (qkv == 1) ? kb : vb) + h*128;
    float* base = (qkv == 0) ? Qo : (qkv == 1) ? Ko : Vo;

    const int tx = tid & 15, ty = tid >> 4;      // TPN=16, TPM=8

    float acc[8][8];
    #pragma unroll
    for (int i = 0; i < 8; ++i)
        #pragma unroll
        for (int j = 0; j < 8; ++j) acc[i][j] = 0.f;

    float4 ra4;        // 64*2 = 128 items, 1 per thread
    float4 rb4[2];     // 8*32 = 256 items, 2 per thread

    auto fetch = [&](int k0){
        {
            int kk4 = tid & 1, mm = tid >> 1;
            ra4 = *(const float4*)(H + (size_t)(row0 + mm)*128 + k0 + kk4*4);
        }
        #pragma unroll
        for (int u = 0; u < 2; ++u){
            int i = tid + u*128;
            int kk = i >> 5, nn4 = i & 31;
            rb4[u] = *(const float4*)(W + (size_t)(k0 + kk)*128 + nn4*4);
        }
    };
    auto stage = [&](int sIdx){
        {
            int kk4 = tid & 1, mm = tid >> 1;
            As[sIdx][kk4*4+0][mm] = ra4.x;
            As[sIdx][kk4*4+1][mm] = ra4.y;
            As[sIdx][kk4*4+2][mm] = ra4.z;
            As[sIdx][kk4*4+3][mm] = ra4.w;
        }
        #pragma unroll
        for (int u = 0; u < 2; ++u){
            int i = tid + u*128;
            int kk = i >> 5, nn4 = i & 31;
            *(float4*)&Bs[sIdx][kk][nn4*4] = rb4[u];
        }
    };

    fetch(0);
    stage(0);
    __syncthreads();

    #pragma unroll 1
    for (int t = 0; t < 16; ++t){
        int cur = t & 1, nxt = cur ^ 1;
        if (t + 1 < 16) fetch((t + 1) * 8);
        #pragma unroll
        for (int kk = 0; kk < 8; ++kk){
            float a[8], b[8];
            #pragma unroll
            for (int i = 0; i < 8; i += 4)
                *(float4*)&a[i] = *(const float4*)&As[cur][kk][ty*8 + i];
            #pragma unroll
            for (int j = 0; j < 8; j += 4)
                *(float4*)&b[j] = *(const float4*)&Bs[cur][kk][tx*8 + j];
            #pragma unroll
            for (int i = 0; i < 8; ++i)
                #pragma unroll
                for (int j = 0; j < 8; ++j)
                    acc[i][j] += a[i]*b[j];
        }
        if (t + 1 < 16) stage(nxt);
        __syncthreads();
    }

    #pragma unroll
    for (int i = 0; i < 8; ++i){
        int gr = row0 + ty*8 + i;
        int bb = gr / 168, nn = gr - bb*168;
        float* dst = base + (((size_t)(bb*4 + h))*168 + nn)*128 + tx*8;
        #pragma unroll
        for (int j4 = 0; j4 < 8; j4 += 4){
            int gn = tx*8 + j4;
            float4 v;
            v.x = acc[i][j4+0] + bias[gn+0];
            v.y = acc[i][j4+1] + bias[gn+1];
            v.z = acc[i][j4+2] + bias[gn+2];
            v.w = acc[i][j4+3] + bias[gn+3];
            *(float4*)(dst + j4) = v;
        }
    }
}

// ---------------- warp-per-row softmax over rows of length 168 ----------------
__global__ void softmax_kernel(float* __restrict__ S, int nrows){
    int gw   = (blockIdx.x * blockDim.x + threadIdx.x) >> 5;
    int lane = threadIdx.x & 31;
    if (gw >= nrows) return;
    float* row = S + (size_t)gw * 168;
    float v[6];
    float mx = -3.4e38f;
    #pragma unroll
    for (int u = 0; u < 6; ++u){
        int idx = lane + u*32;
        v[u] = (idx < 168) ? row[idx] : -3.4e38f;
        mx = fmaxf(mx, v[u]);
    }
    #pragma unroll
    for (int o = 16; o > 0; o >>= 1)
        mx = fmaxf(mx, __shfl_xor_sync(0xffffffffu, mx, o));
    float sum = 0.f;
    #pragma unroll
    for (int u = 0; u < 6; ++u){
        v[u] = expf(v[u] - mx);
        sum += v[u];
    }
    #pragma unroll
    for (int o = 16; o > 0; o >>= 1)
        sum += __shfl_xor_sync(0xffffffffu, sum, o);
    float inv = 1.0f / sum;
    #pragma unroll
    for (int u = 0; u < 6; ++u){
        int idx = lane + u*32;
        if (idx < 168) row[idx] = v[u] * inv;
    }
}

// ---------------- final FC ----------------
__global__ void fc_kernel(const float* __restrict__ O, const float* __restrict__ fcw,
                          const float* __restrict__ fcb, float* __restrict__ out){
    __shared__ float red[256];
    int b = blockIdx.x;
    const float* Ob = O + (size_t)b * 86016;
    int tid = threadIdx.x;
    float acc = 0.f;
    for (int i = tid; i < 86016; i += 256){
        int h = i / 21504;
        int r2 = i - h*21504;
        int n = r2 >> 7, e = r2 & 127;
        acc += Ob[i] * fcw[n*512 + h*128 + e];
    }
    red[tid] = acc; __syncthreads();
    #pragma unroll
    for (int o = 128; o > 0; o >>= 1){ if (tid < o) red[tid] += red[tid+o]; __syncthreads(); }
    if (tid == 0) out[b] = red[0] + fcb[0];
}

// ---------------- host launcher ----------------
extern "C" void kernel_launch(void* const* d_in, const int* in_sizes, int n_in,
                              void* d_out, int out_size){
    const float* X      = (const float*)d_in[0];
    const float* spa_w1 = (const float*)d_in[1];
    const float* spa_b1 = (const float*)d_in[2];
    const float* spa_w2 = (const float*)d_in[3];
    const float* spa_b2 = (const float*)d_in[4];
    const float* tem_w1 = (const float*)d_in[5];
    const float* tem_b1 = (const float*)d_in[6];
    const float* tem_w2 = (const float*)d_in[7];
    const float* tem_b2 = (const float*)d_in[8];
    const float* sgnn_w = (const float*)d_in[9];
    const float* sgnn_b = (const float*)d_in[10];
    const float* tgnn_w = (const float*)d_in[11];
    const float* tgnn_b = (const float*)d_in[12];
    const float* q_w    = (const float*)d_in[13];
    const float* q_b    = (const float*)d_in[14];
    const float* k_w    = (const float*)d_in[15];
    const float* k_b    = (const float*)d_in[16];
    const float* v_w    = (const float*)d_in[17];
    const float* v_b    = (const float*)d_in[18];
    const float* fc_w   = (const float*)d_in[19];
    const float* fc_b   = (const float*)d_in[20];
    float* out = (float*)d_out;

    float *Xf,*T1,*As_,*T2,*At,*Ms,*Mt,*H,*Q,*Kb,*V,*S,*O;
    cudaGetSymbolAddress((void**)&Xf,  g_Xf);
    cudaGetSymbolAddress((void**)&T1,  g_T1);
    cudaGetSymbolAddress((void**)&As_, g_As);
    cudaGetSymbolAddress((void**)&T2,  g_T2);
    cudaGetSymbolAddress((void**)&At,  g_At);
    cudaGetSymbolAddress((void**)&Ms,  g_Ms);
    cudaGetSymbolAddress((void**)&Mt,  g_Mt);
    cudaGetSymbolAddress((void**)&H,   g_H);
    cudaGetSymbolAddress((void**)&Q,   g_Q);
    cudaGetSymbolAddress((void**)&Kb,  g_K);
    cudaGetSymbolAddress((void**)&V,   g_V);
    cudaGetSymbolAddress((void**)&S,   g_S);
    cudaGetSymbolAddress((void**)&O,   g_O);

    const float inv_sqrt_hg = 0.08838834764831845f; // 1/sqrt(128)

    // K1: features, K2: cumsum+normalize
    feat_kernel<<<BSZ*PP, 128>>>(X, Xf);
    cum_norm_kernel<<<BSZ, 256>>>(Xf);

    // (a) T1 = tanh(Xt @ spa_w1 + spa_b1)  (40x128)@(128x64), A transposed
    GA<<<dim3(1,1,BSZ), 40>>>(Xf, 5120, 1, 40, 1,  spa_w1, 0, 64, 1, 1,
                              spa_b1, 0,  T1, 2560, 64,  40, 64, 128, 1.f, 1);
    // (b) A_s = T1 @ spa_w2 + spa_b2      (40x64)@(64x40)
    GSML<<<dim3(1,1,BSZ), 64>>>(T1, 2560, 64, 1, 1,  spa_w2, 0, 40, 1, 1,
                                spa_b2, 0,  As_, 1600, 40,  40, 40, 64, 1.f, 0);
    // (c) T2 = tanh(Xf @ tem_w1 + tem_b1) (128x40)@(40x64)
    GSML<<<dim3(1,2,BSZ), 64>>>(Xf, 5120, 40, 1, 1,  tem_w1, 0, 64, 1, 1,
                                tem_b1, 0,  T2, 8192, 64,  128, 64, 40, 1.f, 1);
    // (d) A_t = T2 @ tem_w2 + tem_b2      (128x64)@(64x128)
    GBIG<<<dim3(1,2,BSZ), 128>>>(T2, 8192, 64, 1, 1,  tem_w2, 0, 128, 1, 1,
                                 tem_b2, 0,  At, 16384, 128,  128, 128, 64, 1.f, 0);
    // (e) M_s = A_s @ Xt                  (40x40)@(40x128), B batched transposed
    GE<<<dim3(1,1,BSZ), 80>>>(As_, 1600, 40, 1, 1,  Xf, 5120, 1, 40, 0,
                              (const float*)0, 0,  Ms, 5120, 128,  40, 128, 40, 1.f, 0);
    // (f) H_s = leaky(M_s @ sgnn_w + b)   (40x128)@(128x128) -> H rows 0..39
    GF<<<dim3(1,1,BSZ), 80>>>(Ms, 5120, 128, 1, 1,  sgnn_w, 0, 128, 1, 1,
                              sgnn_b, 0,  H, 21504, 128,  40, 128, 128, 1.f, 2);
    // (g) M_t = A_t @ Xf                  (128x128)@(128x40), B batched
    GG<<<dim3(1,1,BSZ), 80>>>(At, 16384, 128, 1, 1,  Xf, 5120, 40, 1, 0,
                              (const float*)0, 0,  Mt, 5120, 40,  128, 40, 128, 1.f, 0);
    // (h) H_t = leaky(M_t @ tgnn_w + b)   (128x40)@(40x128) -> H rows 40..167
    GBIG<<<dim3(1,2,BSZ), 128>>>(Mt, 5120, 40, 1, 1,  tgnn_w, 0, 128, 1, 1,
                                 tgnn_b, 0,  H + 40*128, 21504, 128,  128, 128, 40, 1.f, 2);

    // (i) QKV: single stacked launch, zero M-padding (172032 = 2688*64)
    qkv_gemm<<<dim3(2688,12), 128>>>(H, q_w, k_w, v_w, q_b, k_b, v_b, Q, Kb, V);

    // (j) scores = Q @ K^T / sqrt(128)    (168x128)@(128x168); BM=56 exact rows
    GJ<<<dim3(3,3,BSZ*NHH), 56>>>(Q, 21504, 128, 1, 1,  Kb, 21504, 1, 128, 0,
                                  (const float*)0, 0,  S, 28224, 168,  168, 168, 128, inv_sqrt_hg, 0);
    // (k) softmax rows (warp per row)
    {
        int nrows = BSZ*NHH*NNODE;
        int nblk = (nrows*32 + 255) / 256;
        softmax_kernel<<<nblk, 256>>>(S, nrows);
    }
    // (l) O = attn @ V                    (168x168)@(168x128); BM=56 exact rows
    GL<<<dim3(1,3,BSZ*NHH), 112>>>(S, 28224, 168, 1, 1,  V, 21504, 128, 1, 0,
                                   (const float*)0, 0,  O, 21504, 128,  168, 128, 168, 1.f, 0);
    // (m) final FC
    fc_kernel<<<BSZ, 256>>>(O, fc_w, fc_b, out);
}

// round 14
// speedup vs baseline: 1.5301x; 1.5301x over previous
#include <cuda_runtime.h>
#include <math.h>
#include <cstdint>

#define BSZ 1024
#define PP  128
#define SSZ 128
#define NNODE 168
#define NHH 4
#define HGG 128

// ---------------- static scratch (allocation-free rule) ----------------
__device__ float g_Xf[BSZ*PP*40];
__device__ float g_T1[BSZ*40*64];
__device__ float g_As[BSZ*40*40];
__device__ float g_T2[BSZ*PP*64];
__device__ float g_At[BSZ*PP*PP];
__device__ float g_Ms[BSZ*40*PP];
__device__ float g_Mt[BSZ*PP*40];
__device__ float g_H [BSZ*NNODE*HGG];
__device__ float g_Q [BSZ*NHH*NNODE*HGG];
__device__ float g_K [BSZ*NHH*NNODE*HGG];
__device__ float g_V [BSZ*NHH*NNODE*HGG];
__device__ float g_S [BSZ*NHH*NNODE*NNODE];
__device__ float g_O [BSZ*NHH*NNODE*HGG];

// ---------------- block reduction helpers (128 threads) ----------------
__device__ __forceinline__ float4 bsum4(float4 v, float4* red){
    int tid = threadIdx.x;
    __syncthreads();
    red[tid] = v;
    __syncthreads();
    #pragma unroll
    for (int o = 64; o > 0; o >>= 1){
        if (tid < o){
            float4 a = red[tid], b = red[tid+o];
            a.x += b.x; a.y += b.y; a.z += b.z; a.w += b.w;
            red[tid] = a;
        }
        __syncthreads();
    }
    return red[0];
}

__device__ __forceinline__ float2 bmax2(float2 v, float4* red){
    int tid = threadIdx.x;
    __syncthreads();
    red[tid] = make_float4(v.x, v.y, 0.f, 0.f);
    __syncthreads();
    #pragma unroll
    for (int o = 64; o > 0; o >>= 1){
        if (tid < o){
            red[tid].x = fmaxf(red[tid].x, red[tid+o].x);
            red[tid].y = fmaxf(red[tid].y, red[tid+o].y);
        }
        __syncthreads();
    }
    return make_float2(red[0].x, red[0].y);
}

// ---------------- K1: per-row feature extraction ----------------
__global__ void feat_kernel(const float* __restrict__ X, float* __restrict__ Xf){
    __shared__ float s[128], ctab[128], stab[128], psd[128], av[128];
    __shared__ float4 red[128];
    __shared__ float sel[2];
    int row = blockIdx.x;
    int tid = threadIdx.x;

    float x = X[(size_t)row*128 + tid];
    s[tid] = x;
    float sv, cv;
    sincospif((float)tid * (1.0f/64.0f), &sv, &cv);
    ctab[tid] = cv; stab[tid] = sv;

    float2 mm2 = bmax2(make_float2(x, -x), red);
    float mx = mm2.x, mn = -mm2.y;

    float xc  = fminf(fmaxf(x, -0.99999988f), 0.99999988f);
    float asn = asinf(xc);
    float atn = atanf(x);
    float4 r1 = bsum4(make_float4(x, x*x, asn, atn), red);
    float mean    = r1.x * (1.0f/128.0f);
    float rms     = sqrtf(r1.y * (1.0f/128.0f));
    float mean_as = r1.z * (1.0f/128.0f);
    float mean_at = r1.w * (1.0f/128.0f);

    float cen = x - mean;
    float c2  = cen*cen;
    float e   = expf(x - mx);
    float4 r2 = bsum4(make_float4(c2, c2*cen, c2*c2, e), red);
    float var  = r2.x * (1.0f/127.0f);
    float stdv = sqrtf(var);
    float se   = r2.w;

    float da = asn - mean_as, dt = atn - mean_at;
    float4 r3 = bsum4(make_float4(e*x, da*da, dt*dt, 0.f), red);
    float ent      = (mx + logf(se)) - r3.x / se;
    float std_asin = sqrtf(r3.y * (1.0f/127.0f));
    float std_atan = sqrtf(r3.z * (1.0f/127.0f));
    float kurt = (r2.z * (1.0f/128.0f)) / (var*var)  - 3.0f;
    float skew = (r2.y * (1.0f/128.0f)) / (var*stdv);

    if (tid <= 64){
        float re = 0.f, im = 0.f;
        int j = 0;
        #pragma unroll 8
        for (int t = 0; t < 128; ++t){
            float st = s[t];
            re += st * ctab[j];
            im -= st * stab[j];
            j = (j + tid) & 127;
        }
        float a2 = re*re + im*im;
        av[tid]  = sqrtf(a2);
        psd[tid] = a2 * (1.0f/128.0f);
    }
    __syncthreads();
    if (tid > 64){ psd[tid] = psd[128-tid]; av[tid] = av[128-tid]; }
    __syncthreads();

    float pj = psd[tid];
    float aj = av[tid];
    float fj = (float)((tid < 64) ? tid : tid - 128) * (1.0f/128.0f);
    float4 r4 = bsum4(make_float4(pj, pj*pj, fj*pj, 0.f), red);
    float psum      = r4.x;
    float mean_freq = r4.z / psum;
    float pbw       = sqrtf(r4.y / psum);
    float2 m2 = bmax2(make_float2(pj, aj), red);
    float max_psd = m2.x, max_amp = m2.y;

    int rank = 0, gc = 0;
    #pragma unroll 4
    for (int i = 0; i < 128; ++i){
        float pi = psd[i];
        rank += (pi < pj) || (pi == pj && i < tid);
        float ai = av[i];
        gc   += (ai > aj) || (ai == aj && i < tid);
    }
    if (rank == 64) sel[0] = fj;
    if (gc == 0)    sel[1] = fj;
    __syncthreads();

    if (tid == 0){
        float* o = Xf + (size_t)row*40;
        o[0]=mx; o[1]=mn; o[2]=stdv; o[3]=rms; o[4]=mean; o[5]=mx-mn; o[6]=var;
        o[7]=ent; o[8]=std_asin; o[9]=std_atan; o[10]=kurt; o[11]=skew;
        o[12]=mean_freq; o[13]=sel[0]; o[14]=psum; o[15]=1.0f; o[16]=pbw;
        o[17]=max_psd; o[18]=max_amp; o[19]=sel[1];
    }
}

// ---------------- K2: cumsum features + per-batch L2 normalization ----------------
__global__ void cum_norm_kernel(float* __restrict__ Xf){
    __shared__ float red[256];
    int b = blockIdx.x;
    float* F = Xf + (size_t)b*5120;
    int tid = threadIdx.x;
    if (tid < 20){
        float c = 0.f;
        for (int p = 0; p < 128; ++p){
            c += F[p*40 + tid];
            F[p*40 + 20 + tid] = c / sqrtf(fmaxf(fabsf(c), 1e-12f));
        }
    }
    __syncthreads();
    float ss = 0.f;
    for (int i = tid; i < 5120; i += 256){ float v = F[i]; ss += v*v; }
    red[tid] = ss; __syncthreads();
    #pragma unroll
    for (int o = 128; o > 0; o >>= 1){ if (tid < o) red[tid] += red[tid+o]; __syncthreads(); }
    float inv = 1.0f / sqrtf(red[0]);
    for (int i = tid; i < 5120; i += 256) F[i] *= inv;
}

// ---------------- templated strided batched GEMM, double-buffered, vectorized ----------------
// (R11 version: unguarded staging, NT divides BM*BK and BN*BK at every instantiation)
template<int BM, int BN, int BK, int TM, int TN, bool AV, bool BV>
__global__ void __launch_bounds__((BM/TM)*(BN/TN)) bgemm_t(
    const float* __restrict__ A, long long sAb, int sAr, int sAc, int aDiv,
    const float* __restrict__ B, long long sBb, int sBr, int sBc, int bMod,
    const float* __restrict__ bias, int biasStride,
    float* __restrict__ C, long long sCb, int ldc,
    int M, int N, int K, float alpha, int act)
{
    constexpr int TPN = BN / TN;
    constexpr int TPM = BM / TM;
    constexpr int NT  = TPN * TPM;
    constexpr int AL  = (BM*BK)/NT;
    constexpr int BL  = (BN*BK)/NT;
    constexpr int AL4 = AL/4;
    constexpr int BL4 = BL/4;
    constexpr int BK4 = BK/4;
    constexpr int BN4 = BN/4;
    __shared__ float As[2][BK][BM+4];
    __shared__ float Bs[2][BK][BN+4];

    int z = blockIdx.z;
    const float* Ab = A + (size_t)((aDiv > 1) ? (z / aDiv) : z) * (size_t)sAb;
    const float* Bb = B + (size_t)((bMod == 0) ? z : (z % bMod)) * (size_t)sBb;
    const float* biasb = bias ? (bias + (size_t)((bMod > 1) ? (z % bMod) : 0) * (size_t)biasStride) : (const float*)0;
    float* Cb = C + (size_t)z * (size_t)sCb;

    int row0 = blockIdx.y * BM, col0 = blockIdx.x * BN;
    int tid = threadIdx.x;
    int tx = tid % TPN, ty = tid / TPN;

    float acc[TM][TN];
    #pragma unroll
    for (int i = 0; i < TM; ++i)
        #pragma unroll
        for (int j = 0; j < TN; ++j) acc[i][j] = 0.f;

    float4 ra4[AV ? AL4 : 1];
    float  ra [AV ? 1 : AL];
    float4 rb4[BV ? BL4 : 1];
    float  rb [BV ? 1 : BL];

    auto fetch = [&](int k0){
        if constexpr (AV){
            #pragma unroll
            for (int u = 0; u < AL4; ++u){
                int i = tid + u*NT;
                int kk4 = i % BK4, mm = i / BK4;
                int gm = row0 + mm;
                ra4[u] = (gm < M) ? *(const float4*)(Ab + (size_t)gm*sAr + (k0 + kk4*4))
                                  : make_float4(0.f,0.f,0.f,0.f);
            }
        } else {
            #pragma unroll
            for (int u = 0; u < AL; ++u){
                int i = tid + u*NT;
                int kk = i / BM, mm = i % BM;
                int gm = row0 + mm, gk = k0 + kk;
                ra[u] = (gm < M) ? Ab[(size_t)gm*sAr + (size_t)gk*sAc] : 0.f;
            }
        }
        if constexpr (BV){
            #pragma unroll
            for (int u = 0; u < BL4; ++u){
                int i = tid + u*NT;
                int kk = i / BN4, nn4 = i % BN4;
                int gn = col0 + nn4*4, gk = k0 + kk;
                rb4[u] = (gn < N) ? *(const float4*)(Bb + (size_t)gk*sBr + gn)
                                  : make_float4(0.f,0.f,0.f,0.f);
            }
        } else {
            #pragma unroll
            for (int u = 0; u < BL; ++u){
                int i = tid + u*NT;
                int kk = i / BN, nn = i % BN;
                int gn = col0 + nn, gk = k0 + kk;
                rb[u] = (gn < N) ? Bb[(size_t)gk*sBr + (size_t)gn*sBc] : 0.f;
            }
        }
    };
    auto stage = [&](int sIdx){
        if constexpr (AV){
            #pragma unroll
            for (int u = 0; u < AL4; ++u){
                int i = tid + u*NT;
                int kk4 = i % BK4, mm = i / BK4;
                As[sIdx][kk4*4+0][mm] = ra4[u].x;
                As[sIdx][kk4*4+1][mm] = ra4[u].y;
                As[sIdx][kk4*4+2][mm] = ra4[u].z;
                As[sIdx][kk4*4+3][mm] = ra4[u].w;
            }
        } else {
            #pragma unroll
            for (int u = 0; u < AL; ++u){
                int i = tid + u*NT;
                As[sIdx][i / BM][i % BM] = ra[u];
            }
        }
        if constexpr (BV){
            #pragma unroll
            for (int u = 0; u < BL4; ++u){
                int i = tid + u*NT;
                int kk = i / BN4, nn4 = i % BN4;
                *(float4*)&Bs[sIdx][kk][nn4*4] = rb4[u];
            }
        } else {
            #pragma unroll
            for (int u = 0; u < BL; ++u){
                int i = tid + u*NT;
                Bs[sIdx][i / BN][i % BN] = rb[u];
            }
        }
    };

    fetch(0);
    stage(0);
    __syncthreads();

    int nk = K / BK;
    for (int t = 0; t < nk; ++t){
        int cur = t & 1, nxt = cur ^ 1;
        if (t + 1 < nk) fetch((t + 1) * BK);
        #pragma unroll
        for (int kk = 0; kk < BK; ++kk){
            float a[TM], b[TN];
            #pragma unroll
            for (int i = 0; i < TM; i += 4)
                *(float4*)&a[i] = *(const float4*)&As[cur][kk][ty*TM + i];
            #pragma unroll
            for (int j = 0; j < TN; j += 4)
                *(float4*)&b[j] = *(const float4*)&Bs[cur][kk][tx*TN + j];
            #pragma unroll
            for (int i = 0; i < TM; ++i)
                #pragma unroll
                for (int j = 0; j < TN; ++j)
                    acc[i][j] += a[i]*b[j];
        }
        if (t + 1 < nk) stage(nxt);
        __syncthreads();
    }

    #pragma unroll
    for (int i = 0; i < TM; ++i){
        int gm = row0 + ty*TM + i;
        if (gm >= M) continue;
        #pragma unroll
        for (int j4 = 0; j4 < TN; j4 += 4){
            int gn = col0 + tx*TN + j4;
            if (gn >= N) continue;
            float4 v;
            float* vp = &v.x;
            #pragma unroll
            for (int c = 0; c < 4; ++c){
                float w = acc[i][j4+c] * alpha;
                if (biasb) w += biasb[gn+c];
                if (act == 1)      w = tanhf(w);
                else if (act == 2) w = (w >= 0.f) ? w : 0.01f*w;
                vp[c] = w;
            }
            *(float4*)(Cb + (size_t)gm*ldc + gn) = v;
        }
    }
}

#define GBIG  bgemm_t<64,128,8,8,8,true,true>
#define GBIGE bgemm_t<64,128,8,8,8,true,false>
#define GSML  bgemm_t<64,64,8,8,8,true,true>
#define GSMLA bgemm_t<64,64,8,8,8,false,true>
#define GSMLJ bgemm_t<64,64,8,8,8,true,false>

// ---------------- stacked QKV GEMM (verified in R13, zero padding) ----------------
// grid (2688, 12): x = 64-row tile of stacked H (172032x128), y = qkv*4+h.
// C scatter: row gr -> b=gr/168, n=gr%168; dst[((b*4+h)*168+n)*128 + col].
__global__ void __launch_bounds__(128) qkv_gemm(
    const float* __restrict__ H,
    const float* __restrict__ qw, const float* __restrict__ kw, const float* __restrict__ vw,
    const float* __restrict__ qb, const float* __restrict__ kb, const float* __restrict__ vb,
    float* __restrict__ Qo, float* __restrict__ Ko, float* __restrict__ Vo)
{
    __shared__ float As[2][8][68];
    __shared__ float Bs[2][8][132];
    const int tid = threadIdx.x;
    const int row0 = blockIdx.x * 64;
    const int y = blockIdx.y;
    const int qkv = y >> 2, h = y & 3;
    const float* W    = ((qkv == 0) ? qw : (qkv == 1) ? kw : vw) + h*16384;  // [k][n], n contiguous
    const float* bias = ((qkv == 0) ? qb : (qkv == 1) ? kb : vb) + h*128;
    float* base = (qkv == 0) ? Qo : (qkv == 1) ? Ko : Vo;

    const int tx = tid & 15, ty = tid >> 4;      // TPN=16, TPM=8

    float acc[8][8];
    #pragma unroll
    for (int i = 0; i < 8; ++i)
        #pragma unroll
        for (int j = 0; j < 8; ++j) acc[i][j] = 0.f;

    float4 ra4;        // 64 rows * 2 vec-chunks = 128 items, 1 per thread
    float4 rb4[2];     // 8 k * 32 vec-chunks = 256 items, 2 per thread

    auto fetch = [&](int k0){
        {
            int kk4 = tid & 1, mm = tid >> 1;
            ra4 = *(const float4*)(H + (size_t)(row0 + mm)*128 + k0 + kk4*4);
        }
        #pragma unroll
        for (int u = 0; u < 2; ++u){
            int i = tid + u*128;
            int kk = i >> 5, nn4 = i & 31;
            rb4[u] = *(const float4*)(W + (size_t)(k0 + kk)*128 + nn4*4);
        }
    };
    auto stage = [&](int sIdx){
        {
            int kk4 = tid & 1, mm = tid >> 1;
            As[sIdx][kk4*4+0][mm] = ra4.x;
            As[sIdx][kk4*4+1][mm] = ra4.y;
            As[sIdx][kk4*4+2][mm] = ra4.z;
            As[sIdx][kk4*4+3][mm] = ra4.w;
        }
        #pragma unroll
        for (int u = 0; u < 2; ++u){
            int i = tid + u*128;
            int kk = i >> 5, nn4 = i & 31;
            *(float4*)&Bs[sIdx][kk][nn4*4] = rb4[u];
        }
    };

    fetch(0);
    stage(0);
    __syncthreads();

    #pragma unroll 1
    for (int t = 0; t < 16; ++t){
        int cur = t & 1, nxt = cur ^ 1;
        if (t + 1 < 16) fetch((t + 1) * 8);
        #pragma unroll
        for (int kk = 0; kk < 8; ++kk){
            float a[8], b[8];
            #pragma unroll
            for (int i = 0; i < 8; i += 4)
                *(float4*)&a[i] = *(const float4*)&As[cur][kk][ty*8 + i];
            #pragma unroll
            for (int j = 0; j < 8; j += 4)
                *(float4*)&b[j] = *(const float4*)&Bs[cur][kk][tx*8 + j];
            #pragma unroll
            for (int i = 0; i < 8; ++i)
                #pragma unroll
                for (int j = 0; j < 8; ++j)
                    acc[i][j] += a[i]*b[j];
        }
        if (t + 1 < 16) stage(nxt);
        __syncthreads();
    }

    #pragma unroll
    for (int i = 0; i < 8; ++i){
        int gr = row0 + ty*8 + i;
        int bb = gr / 168, nn = gr - bb*168;
        float* dst = base + (((size_t)(bb*4 + h))*168 + nn)*128 + tx*8;
        #pragma unroll
        for (int j4 = 0; j4 < 8; j4 += 4){
            int gn = tx*8 + j4;
            float4 v;
            v.x = acc[i][j4+0] + bias[gn+0];
            v.y = acc[i][j4+1] + bias[gn+1];
            v.z = acc[i][j4+2] + bias[gn+2];
            v.w = acc[i][j4+3] + bias[gn+3];
            *(float4*)(dst + j4) = v;
        }
    }
}

// ---------------- warp-per-row softmax over rows of length 168 ----------------
__global__ void softmax_kernel(float* __restrict__ S, int nrows){
    int gw   = (blockIdx.x * blockDim.x + threadIdx.x) >> 5;
    int lane = threadIdx.x & 31;
    if (gw >= nrows) return;
    float* row = S + (size_t)gw * 168;
    float v[6];
    float mx = -3.4e38f;
    #pragma unroll
    for (int u = 0; u < 6; ++u){
        int idx = lane + u*32;
        v[u] = (idx < 168) ? row[idx] : -3.4e38f;
        mx = fmaxf(mx, v[u]);
    }
    #pragma unroll
    for (int o = 16; o > 0; o >>= 1)
        mx = fmaxf(mx, __shfl_xor_sync(0xffffffffu, mx, o));
    float sum = 0.f;
    #pragma unroll
    for (int u = 0; u < 6; ++u){
        v[u] = expf(v[u] - mx);
        sum += v[u];
    }
    #pragma unroll
    for (int o = 16; o > 0; o >>= 1)
        sum += __shfl_xor_sync(0xffffffffu, sum, o);
    float inv = 1.0f / sum;
    #pragma unroll
    for (int u = 0; u < 6; ++u){
        int idx = lane + u*32;
        if (idx < 168) row[idx] = v[u] * inv;
    }
}

// ---------------- final FC ----------------
__global__ void fc_kernel(const float* __restrict__ O, const float* __restrict__ fcw,
                          const float* __restrict__ fcb, float* __restrict__ out){
    __shared__ float red[256];
    int b = blockIdx.x;
    const float* Ob = O + (size_t)b * 86016;
    int tid = threadIdx.x;
    float acc = 0.f;
    for (int i = tid; i < 86016; i += 256){
        int h = i / 21504;
        int r2 = i - h*21504;
        int n = r2 >> 7, e = r2 & 127;
        acc += Ob[i] * fcw[n*512 + h*128 + e];
    }
    red[tid] = acc; __syncthreads();
    #pragma unroll
    for (int o = 128; o > 0; o >>= 1){ if (tid < o) red[tid] += red[tid+o]; __syncthreads(); }
    if (tid == 0) out[b] = red[0] + fcb[0];
}

// ---------------- host launcher ----------------
extern "C" void kernel_launch(void* const* d_in, const int* in_sizes, int n_in,
                              void* d_out, int out_size){
    const float* X      = (const float*)d_in[0];
    const float* spa_w1 = (const float*)d_in[1];
    const float* spa_b1 = (const float*)d_in[2];
    const float* spa_w2 = (const float*)d_in[3];
    const float* spa_b2 = (const float*)d_in[4];
    const float* tem_w1 = (const float*)d_in[5];
    const float* tem_b1 = (const float*)d_in[6];
    const float* tem_w2 = (const float*)d_in[7];
    const float* tem_b2 = (const float*)d_in[8];
    const float* sgnn_w = (const float*)d_in[9];
    const float* sgnn_b = (const float*)d_in[10];
    const float* tgnn_w = (const float*)d_in[11];
    const float* tgnn_b = (const float*)d_in[12];
    const float* q_w    = (const float*)d_in[13];
    const float* q_b    = (const float*)d_in[14];
    const float* k_w    = (const float*)d_in[15];
    const float* k_b    = (const float*)d_in[16];
    const float* v_w    = (const float*)d_in[17];
    const float* v_b    = (const float*)d_in[18];
    const float* fc_w   = (const float*)d_in[19];
    const float* fc_b   = (const float*)d_in[20];
    float* out = (float*)d_out;

    float *Xf,*T1,*As_,*T2,*At,*Ms,*Mt,*H,*Q,*Kb,*V,*S,*O;
    cudaGetSymbolAddress((void**)&Xf,  g_Xf);
    cudaGetSymbolAddress((void**)&T1,  g_T1);
    cudaGetSymbolAddress((void**)&As_, g_As);
    cudaGetSymbolAddress((void**)&T2,  g_T2);
    cudaGetSymbolAddress((void**)&At,  g_At);
    cudaGetSymbolAddress((void**)&Ms,  g_Ms);
    cudaGetSymbolAddress((void**)&Mt,  g_Mt);
    cudaGetSymbolAddress((void**)&H,   g_H);
    cudaGetSymbolAddress((void**)&Q,   g_Q);
    cudaGetSymbolAddress((void**)&Kb,  g_K);
    cudaGetSymbolAddress((void**)&V,   g_V);
    cudaGetSymbolAddress((void**)&S,   g_S);
    cudaGetSymbolAddress((void**)&O,   g_O);

    const float inv_sqrt_hg = 0.08838834764831845f; // 1/sqrt(128)

    // K1: features, K2: cumsum+normalize
    feat_kernel<<<BSZ*PP, 128>>>(X, Xf);
    cum_norm_kernel<<<BSZ, 256>>>(Xf);

    // (a) T1 = tanh(Xt @ spa_w1 + spa_b1)   (40x128)@(128x64), A transposed
    GSMLA<<<dim3(1,1,BSZ), 64>>>(Xf, 5120, 1, 40, 1,  spa_w1, 0, 64, 1, 1,
                                 spa_b1, 0,  T1, 2560, 64,  40, 64, 128, 1.f, 1);
    // (b) A_s = T1 @ spa_w2 + spa_b2       (40x64)@(64x40)
    GSML<<<dim3(1,1,BSZ), 64>>>(T1, 2560, 64, 1, 1,  spa_w2, 0, 40, 1, 1,
                                spa_b2, 0,  As_, 1600, 40,  40, 40, 64, 1.f, 0);
    // (c) T2 = tanh(Xf @ tem_w1 + tem_b1)  (128x40)@(40x64)
    GSML<<<dim3(1,2,BSZ), 64>>>(Xf, 5120, 40, 1, 1,  tem_w1, 0, 64, 1, 1,
                                tem_b1, 0,  T2, 8192, 64,  128, 64, 40, 1.f, 1);
    // (d) A_t = T2 @ tem_w2 + tem_b2       (128x64)@(64x128)
    GBIG<<<dim3(1,2,BSZ), 128>>>(T2, 8192, 64, 1, 1,  tem_w2, 0, 128, 1, 1,
                                 tem_b2, 0,  At, 16384, 128,  128, 128, 64, 1.f, 0);
    // (e) M_s = A_s @ Xt                   (40x40)@(40x128), B batched transposed
    GBIGE<<<dim3(1,1,BSZ), 128>>>(As_, 1600, 40, 1, 1,  Xf, 5120, 1, 40, 0,
                                  (const float*)0, 0,  Ms, 5120, 128,  40, 128, 40, 1.f, 0);
    // (f) H_s = leaky(M_s @ sgnn_w + b)    (40x128)@(128x128) -> H rows 0..39
    GBIG<<<dim3(1,1,BSZ), 128>>>(Ms, 5120, 128, 1, 1,  sgnn_w, 0, 128, 1, 1,
                                 sgnn_b, 0,  H, 21504, 128,  40, 128, 128, 1.f, 2);
    // (g) M_t = A_t @ Xf                   (128x128)@(128x40), B batched
    GSML<<<dim3(1,2,BSZ), 64>>>(At, 16384, 128, 1, 1,  Xf, 5120, 40, 1, 0,
                                (const float*)0, 0,  Mt, 5120, 40,  128, 40, 128, 1.f, 0);
    // (h) H_t = leaky(M_t @ tgnn_w + b)    (128x40)@(40x128) -> H rows 40..167
    GBIG<<<dim3(1,2,BSZ), 128>>>(Mt, 5120, 40, 1, 1,  tgnn_w, 0, 128, 1, 1,
                                 tgnn_b, 0,  H + 40*128, 21504, 128,  128, 128, 40, 1.f, 2);

    // (i) QKV: single stacked launch, zero M-padding (172032 = 2688*64)
    qkv_gemm<<<dim3(2688,12), 128>>>(H, q_w, k_w, v_w, q_b, k_b, v_b, Q, Kb, V);

    // (j) scores = Q @ K^T / sqrt(128)     (168x128)@(128x168)
    GSMLJ<<<dim3(3,3,BSZ*NHH), 64>>>(Q, 21504, 128, 1, 1,  Kb, 21504, 1, 128, 0,
                                     (const float*)0, 0,  S, 28224, 168,  168, 168, 128, inv_sqrt_hg, 0);
    // (k) softmax rows (warp per row)
    {
        int nrows = BSZ*NHH*NNODE;
        int nblk = (nrows*32 + 255) / 256;
        softmax_kernel<<<nblk, 256>>>(S, nrows);
    }
    // (l) O = attn @ V                     (168x168)@(168x128)
    GBIG<<<dim3(1,3,BSZ*NHH), 128>>>(S, 28224, 168, 1, 1,  V, 21504, 128, 1, 0,
                                     (const float*)0, 0,  O, 21504, 128,  168, 128, 168, 1.f, 0);
    // (m) final FC
    fc_kernel<<<BSZ, 256>>>(O, fc_w, fc_b, out);
}

// round 17
// speedup vs baseline: 1.7769x; 1.1613x over previous
#include <cuda_runtime.h>
#include <math.h>
#include <cstdint>

#define BSZ 1024
#define PP  128
#define SSZ 128
#define NNODE 168
#define NHH 4
#define HGG 128

// ---------------- static scratch (allocation-free rule) ----------------
__device__ float g_Xf[BSZ*PP*40];
__device__ float g_T1[BSZ*40*64];
__device__ float g_As[BSZ*40*40];
__device__ float g_T2[BSZ*PP*64];
__device__ float g_At[BSZ*PP*PP];
__device__ float g_Ms[BSZ*40*PP];
__device__ float g_Mt[BSZ*PP*40];
__device__ float g_H [BSZ*NNODE*HGG];
__device__ float g_Q [BSZ*NHH*NNODE*HGG];
__device__ float g_K [BSZ*NHH*NNODE*HGG];
__device__ float g_V [BSZ*NHH*NNODE*HGG];
__device__ float g_S [BSZ*NHH*NNODE*NNODE];
__device__ float g_O [BSZ*NHH*NNODE*HGG];

// ---------------- block reduction helpers (128 threads) ----------------
__device__ __forceinline__ float4 bsum4(float4 v, float4* red){
    int tid = threadIdx.x;
    __syncthreads();
    red[tid] = v;
    __syncthreads();
    #pragma unroll
    for (int o = 64; o > 0; o >>= 1){
        if (tid < o){
            float4 a = red[tid], b = red[tid+o];
            a.x += b.x; a.y += b.y; a.z += b.z; a.w += b.w;
            red[tid] = a;
        }
        __syncthreads();
    }
    return red[0];
}

__device__ __forceinline__ float2 bmax2(float2 v, float4* red){
    int tid = threadIdx.x;
    __syncthreads();
    red[tid] = make_float4(v.x, v.y, 0.f, 0.f);
    __syncthreads();
    #pragma unroll
    for (int o = 64; o > 0; o >>= 1){
        if (tid < o){
            red[tid].x = fmaxf(red[tid].x, red[tid+o].x);
            red[tid].y = fmaxf(red[tid].y, red[tid+o].y);
        }
        __syncthreads();
    }
    return make_float2(red[0].x, red[0].y);
}

// ---------------- K1: per-row feature extraction ----------------
__global__ void feat_kernel(const float* __restrict__ X, float* __restrict__ Xf){
    __shared__ float s[128], ctab[128], stab[128], psd[128], av[128];
    __shared__ float4 red[128];
    __shared__ float sel[2];
    int row = blockIdx.x;
    int tid = threadIdx.x;

    float x = X[(size_t)row*128 + tid];
    s[tid] = x;
    float sv, cv;
    sincospif((float)tid * (1.0f/64.0f), &sv, &cv);
    ctab[tid] = cv; stab[tid] = sv;

    float2 mm2 = bmax2(make_float2(x, -x), red);
    float mx = mm2.x, mn = -mm2.y;

    float xc  = fminf(fmaxf(x, -0.99999988f), 0.99999988f);
    float asn = asinf(xc);
    float atn = atanf(x);
    float4 r1 = bsum4(make_float4(x, x*x, asn, atn), red);
    float mean    = r1.x * (1.0f/128.0f);
    float rms     = sqrtf(r1.y * (1.0f/128.0f));
    float mean_as = r1.z * (1.0f/128.0f);
    float mean_at = r1.w * (1.0f/128.0f);

    float cen = x - mean;
    float c2  = cen*cen;
    float e   = expf(x - mx);
    float4 r2 = bsum4(make_float4(c2, c2*cen, c2*c2, e), red);
    float var  = r2.x * (1.0f/127.0f);
    float stdv = sqrtf(var);
    float se   = r2.w;

    float da = asn - mean_as, dt = atn - mean_at;
    float4 r3 = bsum4(make_float4(e*x, da*da, dt*dt, 0.f), red);
    float ent      = (mx + logf(se)) - r3.x / se;
    float std_asin = sqrtf(r3.y * (1.0f/127.0f));
    float std_atan = sqrtf(r3.z * (1.0f/127.0f));
    float kurt = (r2.z * (1.0f/128.0f)) / (var*var)  - 3.0f;
    float skew = (r2.y * (1.0f/128.0f)) / (var*stdv);

    if (tid <= 64){
        float re = 0.f, im = 0.f;
        int j = 0;
        #pragma unroll 8
        for (int t = 0; t < 128; ++t){
            float st = s[t];
            re += st * ctab[j];
            im -= st * stab[j];
            j = (j + tid) & 127;
        }
        float a2 = re*re + im*im;
        av[tid]  = sqrtf(a2);
        psd[tid] = a2 * (1.0f/128.0f);
    }
    __syncthreads();
    if (tid > 64){ psd[tid] = psd[128-tid]; av[tid] = av[128-tid]; }
    __syncthreads();

    float pj = psd[tid];
    float aj = av[tid];
    float fj = (float)((tid < 64) ? tid : tid - 128) * (1.0f/128.0f);
    float4 r4 = bsum4(make_float4(pj, pj*pj, fj*pj, 0.f), red);
    float psum      = r4.x;
    float mean_freq = r4.z / psum;
    float pbw       = sqrtf(r4.y / psum);
    float2 m2 = bmax2(make_float2(pj, aj), red);
    float max_psd = m2.x, max_amp = m2.y;

    int rank = 0, gc = 0;
    #pragma unroll 4
    for (int i = 0; i < 128; ++i){
        float pi = psd[i];
        rank += (pi < pj) || (pi == pj && i < tid);
        float ai = av[i];
        gc   += (ai > aj) || (ai == aj && i < tid);
    }
    if (rank == 64) sel[0] = fj;
    if (gc == 0)    sel[1] = fj;
    __syncthreads();

    if (tid == 0){
        float* o = Xf + (size_t)row*40;
        o[0]=mx; o[1]=mn; o[2]=stdv; o[3]=rms; o[4]=mean; o[5]=mx-mn; o[6]=var;
        o[7]=ent; o[8]=std_asin; o[9]=std_atan; o[10]=kurt; o[11]=skew;
        o[12]=mean_freq; o[13]=sel[0]; o[14]=psum; o[15]=1.0f; o[16]=pbw;
        o[17]=max_psd; o[18]=max_amp; o[19]=sel[1];
    }
}

// ---------------- K2: cumsum features + per-batch L2 normalization ----------------
__global__ void cum_norm_kernel(float* __restrict__ Xf){
    __shared__ float red[256];
    int b = blockIdx.x;
    float* F = Xf + (size_t)b*5120;
    int tid = threadIdx.x;
    if (tid < 20){
        float c = 0.f;
        for (int p = 0; p < 128; ++p){
            c += F[p*40 + tid];
            F[p*40 + 20 + tid] = c / sqrtf(fmaxf(fabsf(c), 1e-12f));
        }
    }
    __syncthreads();
    float ss = 0.f;
    for (int i = tid; i < 5120; i += 256){ float v = F[i]; ss += v*v; }
    red[tid] = ss; __syncthreads();
    #pragma unroll
    for (int o = 128; o > 0; o >>= 1){ if (tid < o) red[tid] += red[tid+o]; __syncthreads(); }
    float inv = 1.0f / sqrtf(red[0]);
    for (int i = tid; i < 5120; i += 256) F[i] *= inv;
}

// ---------------- templated strided batched GEMM, double-buffered ----------------
// BMODE: 0 = scalar B (arbitrary strides); 1 = vectorized, B k-major rows (n contiguous, sBr=row stride);
//        2 = vectorized, B n-major rows (k contiguous, sBr=row stride)  [NT GEMM: C=A@B^T]
// All instantiations chosen so every per-thread staging count is exact (no guards on staging index).
template<int BM, int BN, int BK, int TM, int TN, bool AV, int BMODE>
__global__ void __launch_bounds__((BM/TM)*(BN/TN)) bgemm_t(
    const float* __restrict__ A, long long sAb, int sAr, int sAc, int aDiv,
    const float* __restrict__ B, long long sBb, int sBr, int sBc, int bMod,
    const float* __restrict__ bias, int biasStride,
    float* __restrict__ C, long long sCb, int ldc,
    int M, int N, int K, float alpha, int act)
{
    constexpr int TPN = BN / TN;
    constexpr int TPM = BM / TM;
    constexpr int NT  = TPN * TPM;
    constexpr int AL  = (BM*BK)/NT;
    constexpr int AL4 = AL/4;
    constexpr int BK4 = BK/4;
    constexpr int BN4 = BN/4;
    constexpr int BL   = (BMODE == 0) ? (BN*BK)/NT : 1;   // scalar B count
    constexpr int BL4  = (BMODE == 1) ? (BK*BN4)/NT : 1;  // vec k-major count
    constexpr int BLT4 = (BMODE == 2) ? (BN*BK4)/NT : 1;  // vec n-major count
    __shared__ float As[2][BK][BM+4];
    __shared__ float Bs[2][BK][BN+4];

    int z = blockIdx.z;
    const float* Ab = A + (size_t)((aDiv > 1) ? (z / aDiv) : z) * (size_t)sAb;
    const float* Bb = B + (size_t)((bMod == 0) ? z : (z % bMod)) * (size_t)sBb;
    const float* biasb = bias ? (bias + (size_t)((bMod > 1) ? (z % bMod) : 0) * (size_t)biasStride) : (const float*)0;
    float* Cb = C + (size_t)z * (size_t)sCb;

    int row0 = blockIdx.y * BM, col0 = blockIdx.x * BN;
    int tid = threadIdx.x;
    int tx = tid % TPN, ty = tid / TPN;

    float acc[TM][TN];
    #pragma unroll
    for (int i = 0; i < TM; ++i)
        #pragma unroll
        for (int j = 0; j < TN; ++j) acc[i][j] = 0.f;

    float4 ra4[AV ? AL4 : 1];
    float  ra [AV ? 1 : AL];
    float4 rb4[BL4];
    float  rb [BL];
    float4 rbt4[BLT4];

    auto fetch = [&](int k0){
        if constexpr (AV){
            #pragma unroll
            for (int u = 0; u < AL4; ++u){
                int i = tid + u*NT;
                int kk4 = i % BK4, mm = i / BK4;
                int gm = row0 + mm;
                ra4[u] = (gm < M) ? *(const float4*)(Ab + (size_t)gm*sAr + (k0 + kk4*4))
                                  : make_float4(0.f,0.f,0.f,0.f);
            }
        } else {
            #pragma unroll
            for (int u = 0; u < AL; ++u){
                int i = tid + u*NT;
                int kk = i / BM, mm = i % BM;
                int gm = row0 + mm, gk = k0 + kk;
                ra[u] = (gm < M) ? Ab[(size_t)gm*sAr + (size_t)gk*sAc] : 0.f;
            }
        }
        if constexpr (BMODE == 1){
            #pragma unroll
            for (int u = 0; u < BL4; ++u){
                int i = tid + u*NT;
                int kk = i / BN4, nn4 = i % BN4;
                int gn = col0 + nn4*4, gk = k0 + kk;
                rb4[u] = (gn < N) ? *(const float4*)(Bb + (size_t)gk*sBr + gn)
                                  : make_float4(0.f,0.f,0.f,0.f);
            }
        } else if constexpr (BMODE == 2){
            #pragma unroll
            for (int u = 0; u < BLT4; ++u){
                int i = tid + u*NT;
                int nn = i / BK4, kk4 = i % BK4;
                int gn = col0 + nn;
                rbt4[u] = (gn < N) ? *(const float4*)(Bb + (size_t)gn*sBr + (k0 + kk4*4))
                                   : make_float4(0.f,0.f,0.f,0.f);
            }
        } else {
            #pragma unroll
            for (int u = 0; u < BL; ++u){
                int i = tid + u*NT;
                int kk = i / BN, nn = i % BN;
                int gn = col0 + nn, gk = k0 + kk;
                rb[u] = (gn < N) ? Bb[(size_t)gk*sBr + (size_t)gn*sBc] : 0.f;
            }
        }
    };
    auto stage = [&](int sIdx){
        if constexpr (AV){
            #pragma unroll
            for (int u = 0; u < AL4; ++u){
                int i = tid + u*NT;
                int kk4 = i % BK4, mm = i / BK4;
                As[sIdx][kk4*4+0][mm] = ra4[u].x;
                As[sIdx][kk4*4+1][mm] = ra4[u].y;
                As[sIdx][kk4*4+2][mm] = ra4[u].z;
                As[sIdx][kk4*4+3][mm] = ra4[u].w;
            }
        } else {
            #pragma unroll
            for (int u = 0; u < AL; ++u){
                int i = tid + u*NT;
                As[sIdx][i / BM][i % BM] = ra[u];
            }
        }
        if constexpr (BMODE == 1){
            #pragma unroll
            for (int u = 0; u < BL4; ++u){
                int i = tid + u*NT;
                int kk = i / BN4, nn4 = i % BN4;
                *(float4*)&Bs[sIdx][kk][nn4*4] = rb4[u];
            }
        } else if constexpr (BMODE == 2){
            #pragma unroll
            for (int u = 0; u < BLT4; ++u){
                int i = tid + u*NT;
                int nn = i / BK4, kk4 = i % BK4;
                Bs[sIdx][kk4*4+0][nn] = rbt4[u].x;
                Bs[sIdx][kk4*4+1][nn] = rbt4[u].y;
                Bs[sIdx][kk4*4+2][nn] = rbt4[u].z;
                Bs[sIdx][kk4*4+3][nn] = rbt4[u].w;
            }
        } else {
            #pragma unroll
            for (int u = 0; u < BL; ++u){
                int i = tid + u*NT;
                Bs[sIdx][i / BN][i % BN] = rb[u];
            }
        }
    };

    fetch(0);
    stage(0);
    __syncthreads();

    int nk = K / BK;
    for (int t = 0; t < nk; ++t){
        int cur = t & 1, nxt = cur ^ 1;
        if (t + 1 < nk) fetch((t + 1) * BK);
        #pragma unroll
        for (int kk = 0; kk < BK; ++kk){
            float a[TM], b[TN];
            #pragma unroll
            for (int i = 0; i < TM; i += 4)
                *(float4*)&a[i] = *(const float4*)&As[cur][kk][ty*TM + i];
            #pragma unroll
            for (int j = 0; j < TN; j += 4)
                *(float4*)&b[j] = *(const float4*)&Bs[cur][kk][tx*TN + j];
            #pragma unroll
            for (int i = 0; i < TM; ++i)
                #pragma unroll
                for (int j = 0; j < TN; ++j)
                    acc[i][j] += a[i]*b[j];
        }
        if (t + 1 < nk) stage(nxt);
        __syncthreads();
    }

    #pragma unroll
    for (int i = 0; i < TM; ++i){
        int gm = row0 + ty*TM + i;
        if (gm >= M) continue;
        #pragma unroll
        for (int j4 = 0; j4 < TN; j4 += 4){
            int gn = col0 + tx*TN + j4;
            if (gn >= N) continue;
            float4 v;
            float* vp = &v.x;
            #pragma unroll
            for (int c = 0; c < 4; ++c){
                float w = acc[i][j4+c] * alpha;
                if (biasb) w += biasb[gn+c];
                if (act == 1)      w = tanhf(w);
                else if (act == 2) w = (w >= 0.f) ? w : 0.01f*w;
                vp[c] = w;
            }
            *(float4*)(Cb + (size_t)gm*ldc + gn) = v;
        }
    }
}

// Tile variants (all staging counts divide exactly)
#define GBIG  bgemm_t<64,128,8,8,8,true,1>     // 128 thr, 64 acc
#define GBIGE bgemm_t<64,128,8,8,8,true,0>     // (e)
#define GSML  bgemm_t<64,64,8,8,8,true,1>      // 64 thr
#define GSMLA bgemm_t<64,64,8,8,8,false,1>     // (a): A transposed
#define G2BIG bgemm_t<128,64,16,8,4,true,1>    // 256 thr, 32 acc  (d),(g)
#define G2C   bgemm_t<128,64,8,8,4,true,0>     // 256 thr, 32 acc  (c),(h)  K=40
#define GJ2   bgemm_t<64,64,16,8,4,true,2>     // 128 thr, 32 acc  (j) NT-GEMM

// ---------------- stacked QKV GEMM (zero padding) ----------------
__global__ void __launch_bounds__(128) qkv_gemm(
    const float* __restrict__ H,
    const float* __restrict__ qw, const float* __restrict__ kw, const float* __restrict__ vw,
    const float* __restrict__ qb, const float* __restrict__ kb, const float* __restrict__ vb,
    float* __restrict__ Qo, float* __restrict__ Ko, float* __restrict__ Vo)
{
    __shared__ float As[2][8][68];
    __shared__ float Bs[2][8][132];
    const int tid = threadIdx.x;
    const int row0 = blockIdx.x * 64;
    const int y = blockIdx.y;
    const int qkv = y >> 2, h = y & 3;
    const float* W    = ((qkv == 0) ? qw : (qkv == 1) ? kw : vw) + h*16384;
    const float* bias = ((qkv == 0) ? qb : (qkv == 1) ? kb : vb) + h*128;
    float* base = (qkv == 0) ? Qo : (qkv == 1) ? Ko : Vo;

    const int tx = tid & 15, ty = tid >> 4;

    float acc[8][8];
    #pragma unroll
    for (int i = 0; i < 8; ++i)
        #pragma unroll
        for (int j = 0; j < 8; ++j) acc[i][j] = 0.f;

    float4 ra4;
    float4 rb4[2];

    auto fetch = [&](int k0){
        {
            int kk4 = tid & 1, mm = tid >> 1;
            ra4 = *(const float4*)(H + (size_t)(row0 + mm)*128 + k0 + kk4*4);
        }
        #pragma unroll
        for (int u = 0; u < 2; ++u){
            int i = tid + u*128;
            int kk = i >> 5, nn4 = i & 31;
            rb4[u] = *(const float4*)(W + (size_t)(k0 + kk)*128 + nn4*4);
        }
    };
    auto stage = [&](int sIdx){
        {
            int kk4 = tid & 1, mm = tid >> 1;
            As[sIdx][kk4*4+0][mm] = ra4.x;
            As[sIdx][kk4*4+1][mm] = ra4.y;
            As[sIdx][kk4*4+2][mm] = ra4.z;
            As[sIdx][kk4*4+3][mm] = ra4.w;
        }
        #pragma unroll
        for (int u = 0; u < 2; ++u){
            int i = tid + u*128;
            int kk = i >> 5, nn4 = i & 31;
            *(float4*)&Bs[sIdx][kk][nn4*4] = rb4[u];
        }
    };

    fetch(0);
    stage(0);
    __syncthreads();

    #pragma unroll 1
    for (int t = 0; t < 16; ++t){
        int cur = t & 1, nxt = cur ^ 1;
        if (t + 1 < 16) fetch((t + 1) * 8);
        #pragma unroll
        for (int kk = 0; kk < 8; ++kk){
            float a[8], b[8];
            #pragma unroll
            for (int i = 0; i < 8; i += 4)
                *(float4*)&a[i] = *(const float4*)&As[cur][kk][ty*8 + i];
            #pragma unroll
            for (int j = 0; j < 8; j += 4)
                *(float4*)&b[j] = *(const float4*)&Bs[cur][kk][tx*8 + j];
            #pragma unroll
            for (int i = 0; i < 8; ++i)
                #pragma unroll
                for (int j = 0; j < 8; ++j)
                    acc[i][j] += a[i]*b[j];
        }
        if (t + 1 < 16) stage(nxt);
        __syncthreads();
    }

    #pragma unroll
    for (int i = 0; i < 8; ++i){
        int gr = row0 + ty*8 + i;
        int bb = gr / 168, nn = gr - bb*168;
        float* dst = base + (((size_t)(bb*4 + h))*168 + nn)*128 + tx*8;
        #pragma unroll
        for (int j4 = 0; j4 < 8; j4 += 4){
            int gn = tx*8 + j4;
            float4 v;
            v.x = acc[i][j4+0] + bias[gn+0];
            v.y = acc[i][j4+1] + bias[gn+1];
            v.z = acc[i][j4+2] + bias[gn+2];
            v.w = acc[i][j4+3] + bias[gn+3];
            *(float4*)(dst + j4) = v;
        }
    }
}

// ---------------- warp-per-row softmax over rows of length 168 ----------------
__global__ void softmax_kernel(float* __restrict__ S, int nrows){
    int gw   = (blockIdx.x * blockDim.x + threadIdx.x) >> 5;
    int lane = threadIdx.x & 31;
    if (gw >= nrows) return;
    float* row = S + (size_t)gw * 168;
    float v[6];
    float mx = -3.4e38f;
    #pragma unroll
    for (int u = 0; u < 6; ++u){
        int idx = lane + u*32;
        v[u] = (idx < 168) ? row[idx] : -3.4e38f;
        mx = fmaxf(mx, v[u]);
    }
    #pragma unroll
    for (int o = 16; o > 0; o >>= 1)
        mx = fmaxf(mx, __shfl_xor_sync(0xffffffffu, mx, o));
    float sum = 0.f;
    #pragma unroll
    for (int u = 0; u < 6; ++u){
        v[u] = expf(v[u] - mx);
        sum += v[u];
    }
    #pragma unroll
    for (int o = 16; o > 0; o >>= 1)
        sum += __shfl_xor_sync(0xffffffffu, sum, o);
    float inv = 1.0f / sum;
    #pragma unroll
    for (int u = 0; u < 6; ++u){
        int idx = lane + u*32;
        if (idx < 168) row[idx] = v[u] * inv;
    }
}

// ---------------- final FC ----------------
__global__ void fc_kernel(const float* __restrict__ O, const float* __restrict__ fcw,
                          const float* __restrict__ fcb, float* __restrict__ out){
    __shared__ float red[256];
    int b = blockIdx.x;
    const float* Ob = O + (size_t)b * 86016;
    int tid = threadIdx.x;
    float acc = 0.f;
    for (int i = tid; i < 86016; i += 256){
        int h = i / 21504;
        int r2 = i - h*21504;
        int n = r2 >> 7, e = r2 & 127;
        acc += Ob[i] * fcw[n*512 + h*128 + e];
    }
    red[tid] = acc; __syncthreads();
    #pragma unroll
    for (int o = 128; o > 0; o >>= 1){ if (tid < o) red[tid] += red[tid+o]; __syncthreads(); }
    if (tid == 0) out[b] = red[0] + fcb[0];
}

// ---------------- host launcher ----------------
extern "C" void kernel_launch(void* const* d_in, const int* in_sizes, int n_in,
                              void* d_out, int out_size){
    const float* X      = (const float*)d_in[0];
    const float* spa_w1 = (const float*)d_in[1];
    const float* spa_b1 = (const float*)d_in[2];
    const float* spa_w2 = (const float*)d_in[3];
    const float* spa_b2 = (const float*)d_in[4];
    const float* tem_w1 = (const float*)d_in[5];
    const float* tem_b1 = (const float*)d_in[6];
    const float* tem_w2 = (const float*)d_in[7];
    const float* tem_b2 = (const float*)d_in[8];
    const float* sgnn_w = (const float*)d_in[9];
    const float* sgnn_b = (const float*)d_in[10];
    const float* tgnn_w = (const float*)d_in[11];
    const float* tgnn_b = (const float*)d_in[12];
    const float* q_w    = (const float*)d_in[13];
    const float* q_b    = (const float*)d_in[14];
    const float* k_w    = (const float*)d_in[15];
    const float* k_b    = (const float*)d_in[16];
    const float* v_w    = (const float*)d_in[17];
    const float* v_b    = (const float*)d_in[18];
    const float* fc_w   = (const float*)d_in[19];
    const float* fc_b   = (const float*)d_in[20];
    float* out = (float*)d_out;

    float *Xf,*T1,*As_,*T2,*At,*Ms,*Mt,*H,*Q,*Kb,*V,*S,*O;
    cudaGetSymbolAddress((void**)&Xf,  g_Xf);
    cudaGetSymbolAddress((void**)&T1,  g_T1);
    cudaGetSymbolAddress((void**)&As_, g_As);
    cudaGetSymbolAddress((void**)&T2,  g_T2);
    cudaGetSymbolAddress((void**)&At,  g_At);
    cudaGetSymbolAddress((void**)&Ms,  g_Ms);
    cudaGetSymbolAddress((void**)&Mt,  g_Mt);
    cudaGetSymbolAddress((void**)&H,   g_H);
    cudaGetSymbolAddress((void**)&Q,   g_Q);
    cudaGetSymbolAddress((void**)&Kb,  g_K);
    cudaGetSymbolAddress((void**)&V,   g_V);
    cudaGetSymbolAddress((void**)&S,   g_S);
    cudaGetSymbolAddress((void**)&O,   g_O);

    const float inv_sqrt_hg = 0.08838834764831845f; // 1/sqrt(128)

    // K1: features, K2: cumsum+normalize
    feat_kernel<<<BSZ*PP, 128>>>(X, Xf);
    cum_norm_kernel<<<BSZ, 256>>>(Xf);

    // (a) T1 = tanh(Xt @ spa_w1 + spa_b1)   (40x128)@(128x64), A transposed
    GSMLA<<<dim3(1,1,BSZ), 64>>>(Xf, 5120, 1, 40, 1,  spa_w1, 0, 64, 1, 1,
                                 spa_b1, 0,  T1, 2560, 64,  40, 64, 128, 1.f, 1);
    // (b) A_s = T1 @ spa_w2 + spa_b2       (40x64)@(64x40)
    GSML<<<dim3(1,1,BSZ), 64>>>(T1, 2560, 64, 1, 1,  spa_w2, 0, 40, 1, 1,
                                spa_b2, 0,  As_, 1600, 40,  40, 40, 64, 1.f, 0);
    // (c) T2 = tanh(Xf @ tem_w1 + tem_b1)  (128x40)@(40x64), 256-thr tile
    G2C<<<dim3(1,1,BSZ), 256>>>(Xf, 5120, 40, 1, 1,  tem_w1, 0, 64, 1, 1,
                                tem_b1, 0,  T2, 8192, 64,  128, 64, 40, 1.f, 1);
    // (d) A_t = T2 @ tem_w2 + tem_b2       (128x64)@(64x128), BK=16 256-thr
    G2BIG<<<dim3(2,1,BSZ), 256>>>(T2, 8192, 64, 1, 1,  tem_w2, 0, 128, 1, 1,
                                  tem_b2, 0,  At, 16384, 128,  128, 128, 64, 1.f, 0);
    // (e) M_s = A_s @ Xt                   (40x40)@(40x128), B batched transposed
    GBIGE<<<dim3(1,1,BSZ), 128>>>(As_, 1600, 40, 1, 1,  Xf, 5120, 1, 40, 0,
                                  (const float*)0, 0,  Ms, 5120, 128,  40, 128, 40, 1.f, 0);
    // (f) H_s = leaky(M_s @ sgnn_w + b)    (40x128)@(128x128) -> H rows 0..39
    GBIG<<<dim3(1,1,BSZ), 128>>>(Ms, 5120, 128, 1, 1,  sgnn_w, 0, 128, 1, 1,
                                 sgnn_b, 0,  H, 21504, 128,  40, 128, 128, 1.f, 2);
    // (g) M_t = A_t @ Xf                   (128x128)@(128x40), B batched; BK=16 256-thr
    G2BIG<<<dim3(1,1,BSZ), 256>>>(At, 16384, 128, 1, 1,  Xf, 5120, 40, 1, 0,
                                  (const float*)0, 0,  Mt, 5120, 40,  128, 40, 128, 1.f, 0);
    // (h) H_t = leaky(M_t @ tgnn_w + b)    (128x40)@(40x128) -> H rows 40..167; 256-thr
    G2C<<<dim3(2,1,BSZ), 256>>>(Mt, 5120, 40, 1, 1,  tgnn_w, 0, 128, 1, 1,
                                tgnn_b, 0,  H + 40*128, 21504, 128,  128, 128, 40, 1.f, 2);

    // (i) QKV: single stacked launch, zero M-padding (172032 = 2688*64)
    qkv_gemm<<<dim3(2688,12), 128>>>(H, q_w, k_w, v_w, q_b, k_b, v_b, Q, Kb, V);

    // (j) scores = Q @ K^T / sqrt(128)     NT-GEMM: both operands k-contiguous, BK=16
    GJ2<<<dim3(3,3,BSZ*NHH), 128>>>(Q, 21504, 128, 1, 1,  Kb, 21504, 128, 1, 0,
                                    (const float*)0, 0,  S, 28224, 168,  168, 168, 128, inv_sqrt_hg, 0);
    // (k) softmax rows (warp per row)
    {
        int nrows = BSZ*NHH*NNODE;
        int nblk = (nrows*32 + 255) / 256;
        softmax_kernel<<<nblk, 256>>>(S, nrows);
    }
    // (l) O = attn @ V                     (168x168)@(168x128)
    GBIG<<<dim3(1,3,BSZ*NHH), 128>>>(S, 28224, 168, 1, 1,  V, 21504, 128, 1, 0,
                                     (const float*)0, 0,  O, 21504, 128,  168, 128, 168, 1.f, 0);
    // (m) final FC
    fc_kernel<<<BSZ, 256>>>(O, fc_w, fc_b, out);
}